// round 15
// baseline (speedup 1.0000x reference)
#include <cuda_runtime.h>
#include <math.h>

#define BB 64
#define NN 16384
#define CC 64
#define SLABS 16
#define GRID (BB * SLABS)                  // 1024 blocks -> single resident wave
#define THREADS 256
#define NTOT (NN * CC)                     // 1,048,576 floats per sample
#define F4_PER_B (NTOT / 4)                // 262,144 float4 per sample
#define F4_PER_SLAB (F4_PER_B / SLABS)     // 16,384 float4 per slab (256 KB)
#define ITERS (F4_PER_SLAB / THREADS)      // 64
#define TAIL_START (ITERS / 2)             // second half -> L2 evict_last (harvest)

// __device__ scratch (no allocations). Counters MONOTONIC across graph
// replays (never reset); epochs derived from tickets -> replay-safe.
__device__ float g_psum[BB][SLABS][CC];
__device__ float g_psq [BB][SLABS][CC];
__device__ unsigned long long g_done[BB];     // +SLABS per sample per launch
__device__ unsigned long long g_tick[BB];     // +SLABS per sample per launch

// Cache-policy-steered 128-bit loads (createpolicy + L2::cache_hint form,
// which ptxas accepts for v4.f32 on sm_103a).
__device__ __forceinline__ unsigned long long mk_policy_evict_first() {
    unsigned long long p;
    asm("createpolicy.fractional.L2::evict_first.b64 %0, 1.0;" : "=l"(p));
    return p;
}
__device__ __forceinline__ unsigned long long mk_policy_evict_last() {
    unsigned long long p;
    asm("createpolicy.fractional.L2::evict_last.b64 %0, 1.0;" : "=l"(p));
    return p;
}
__device__ __forceinline__ float4 ld_nc_hint(const float4* __restrict__ p,
                                             unsigned long long pol) {
    float4 v;
    asm volatile("ld.global.nc.L2::cache_hint.v4.f32 {%0,%1,%2,%3}, [%4], %5;"
                 : "=f"(v.x), "=f"(v.y), "=f"(v.z), "=f"(v.w)
                 : "l"(p), "l"(pol));
    return v;
}

__global__ __launch_bounds__(THREADS, 8) void fused_kernel(const float* __restrict__ x,
                                                           const float* __restrict__ alpha_u,
                                                           const float* __restrict__ noise,
                                                           const int*   __restrict__ dom,
                                                           const int*   __restrict__ cls,
                                                           float* __restrict__ out) {
    const int tid  = threadIdx.x;
    const int b    = blockIdx.x >> 4;        // / SLABS
    const int slab = blockIdx.x & 15;        // % SLABS
    const float4* __restrict__ x4 = reinterpret_cast<const float4*>(x);
    float4* __restrict__ o4 = reinterpret_cast<float4*>(out);
    const long base = (long)b * F4_PER_B + (long)slab * F4_PER_SLAB;

    __shared__ float4 ssum[THREADS];                    // 4 KB
    __shared__ float4 ssq [THREADS];                    // 4 KB
    __shared__ float4 s_scale4[CC / 4];                 // 16B-aligned by type
    __shared__ float4 s_bias4 [CC / 4];
    __shared__ int    s_idx;
    __shared__ unsigned long long s_target;

    // ---- partner argmax (warp 0) + epoch ticket (warp 1): BEFORE streaming --
    if (tid < 32) {
        const int cb = cls[b];
        const int db = dom[b];
        float best = -INFINITY;
        int   bi   = -1;
        #pragma unroll
        for (int h = 0; h < 2; h++) {
            const int j = h * 32 + tid;
            const bool valid = (cls[j] == cb) && (dom[j] != db);
            float v = valid ? __ldg(&noise[b * BB + j]) : -INFINITY;
            float m = v; int mi = (v == -INFINITY) ? -1 : j;
            #pragma unroll
            for (int off = 16; off > 0; off >>= 1) {
                float om = __shfl_down_sync(0xffffffffu, m, off);
                int   oi = __shfl_down_sync(0xffffffffu, mi, off);
                if (om > m || (om == m && oi >= 0 && (mi < 0 || oi < mi))) { m = om; mi = oi; }
            }
            if (tid == 0) {
                if (m > best || (m == best && mi >= 0 && (bi < 0 || mi < bi))) { best = m; bi = mi; }
            }
        }
        if (tid == 0) s_idx = (bi < 0) ? b : bi;
    }
    if (tid == 32) {
        unsigned long long t = atomicAdd(&g_tick[b], 1ULL);
        s_target = (t / (unsigned long long)SLABS + 1ULL) * (unsigned long long)SLABS;
    }

    // ======= Phase 1: stats (ascending). Head: L2 evict_first (never
    //         harvestable). Tail: L2 evict_last (phase 2 consumes it first). ==
    {
        const unsigned long long pol_first = mk_policy_evict_first();
        const unsigned long long pol_last  = mk_policy_evict_last();
        float4 s = make_float4(0.f, 0.f, 0.f, 0.f);
        float4 q = make_float4(0.f, 0.f, 0.f, 0.f);
        #pragma unroll 8
        for (int k = 0; k < TAIL_START; k++) {
            float4 v = ld_nc_hint(&x4[base + (long)k * THREADS + tid], pol_first);
            s.x += v.x; s.y += v.y; s.z += v.z; s.w += v.w;
            q.x = fmaf(v.x, v.x, q.x);
            q.y = fmaf(v.y, v.y, q.y);
            q.z = fmaf(v.z, v.z, q.z);
            q.w = fmaf(v.w, v.w, q.w);
        }
        #pragma unroll 8
        for (int k = TAIL_START; k < ITERS; k++) {
            float4 v = ld_nc_hint(&x4[base + (long)k * THREADS + tid], pol_last);
            s.x += v.x; s.y += v.y; s.z += v.z; s.w += v.w;
            q.x = fmaf(v.x, v.x, q.x);
            q.y = fmaf(v.y, v.y, q.y);
            q.z = fmaf(v.z, v.z, q.z);
            q.w = fmaf(v.w, v.w, q.w);
        }
        ssum[tid] = s;
        ssq [tid] = q;
    }
    __syncthreads();

    if (tid < 16) {   // 16 channel-quads; fold 16 partials each
        float4 S = make_float4(0.f, 0.f, 0.f, 0.f);
        float4 Q = make_float4(0.f, 0.f, 0.f, 0.f);
        #pragma unroll
        for (int m = 0; m < 16; m++) {
            float4 a = ssum[tid + 16 * m];
            float4 c = ssq [tid + 16 * m];
            S.x += a.x; S.y += a.y; S.z += a.z; S.w += a.w;
            Q.x += c.x; Q.y += c.y; Q.z += c.z; Q.w += c.w;
        }
        const int c0 = tid * 4;
        g_psum[b][slab][c0 + 0] = S.x;
        g_psum[b][slab][c0 + 1] = S.y;
        g_psum[b][slab][c0 + 2] = S.z;
        g_psum[b][slab][c0 + 3] = S.w;
        g_psq [b][slab][c0 + 0] = Q.x;
        g_psq [b][slab][c0 + 1] = Q.y;
        g_psq [b][slab][c0 + 2] = Q.z;
        g_psq [b][slab][c0 + 3] = Q.w;
        __threadfence();                     // partials visible device-wide
    }
    __syncthreads();
    if (tid == 0) atomicAdd(&g_done[b], 1ULL);

    // ---- wait for own + partner stats (single wave -> tight spread) --------
    const int idx = s_idx;
    if (tid == 0) {
        const unsigned long long target = s_target;
        for (;;) {
            unsigned long long va, vb;
            asm volatile("ld.global.acquire.gpu.u64 %0, [%1];"
                         : "=l"(va) : "l"(&g_done[b]) : "memory");
            asm volatile("ld.global.acquire.gpu.u64 %0, [%1];"
                         : "=l"(vb) : "l"(&g_done[idx]) : "memory");
            if (va >= target && vb >= target) break;
            __nanosleep(32);
        }
        __threadfence();
    }
    __syncthreads();

    // ---- scale/bias for sample b (partials are L2-hot) ----------------------
    if (tid < CC) {
        const int c = tid;
        float sum = 0.f, sq = 0.f, sum2 = 0.f, sq2 = 0.f;
        #pragma unroll
        for (int sl = 0; sl < SLABS; sl++) {
            sum  += g_psum[b][sl][c];
            sq   += g_psq [b][sl][c];
            sum2 += g_psum[idx][sl][c];
            sq2  += g_psq [idx][sl][c];
        }
        const float inv_n   = 1.0f / 16384.0f;
        const float inv_nm1 = 1.0f / 16383.0f;
        const float eps = 1e-6f;

        float mu   = sum * inv_n;
        float var  = (sq  - sum  * sum  * inv_n) * inv_nm1;
        float sig  = sqrtf(var + eps);
        float mu2  = sum2 * inv_n;
        float var2 = (sq2 - sum2 * sum2 * inv_n) * inv_nm1;
        float sig2 = sqrtf(var2 + eps);

        float a = alpha_u[b] * 0.5f;         // ALPHA_MAX
        float mu_mix  = mu  * a + mu2  * (1.0f - a);
        float sig_mix = sig * a + sig2 * (1.0f - a);

        float sc = sig_mix / sig;
        reinterpret_cast<float*>(s_scale4)[c] = sc;
        reinterpret_cast<float*>(s_bias4 )[c] = mu_mix - mu * sc;
    }
    __syncthreads();

    // ======= Phase 2: apply, DESCENDING (pinned L2 tail first). Stores are
    //         write-through so they don't displace pinned x lines. ===========
    const int cq = tid & 15;                 // fixed channel-quad per thread
    const float4 scl = s_scale4[cq];
    const float4 bia = s_bias4 [cq];

    #pragma unroll 4
    for (int k = ITERS - 1; k >= 0; k--) {
        const long i4 = base + (long)k * THREADS + tid;
        float4 v = __ldcs(&x4[i4]);          // read-once -> evict-first
        float4 r;
        r.x = fmaf(v.x, scl.x, bia.x);
        r.y = fmaf(v.y, scl.y, bia.y);
        r.z = fmaf(v.z, scl.z, bia.z);
        r.w = fmaf(v.w, scl.w, bia.w);
        __stwt(&o4[i4], r);                  // write-through, no L2 displacement
    }
}

extern "C" void kernel_launch(void* const* d_in, const int* in_sizes, int n_in,
                              void* d_out, int out_size) {
    const float* x       = (const float*)d_in[0];
    const float* alpha_u = (const float*)d_in[1];
    const float* noise   = (const float*)d_in[2];
    const int*   dom     = (const int*)  d_in[3];
    const int*   cls     = (const int*)  d_in[4];
    float* out = (float*)d_out;

    fused_kernel<<<GRID, THREADS>>>(x, alpha_u, noise, dom, cls, out);
}

// round 16
// speedup vs baseline: 1.0012x; 1.0012x over previous
#include <cuda_runtime.h>
#include <math.h>

#define BB 64
#define NN 16384
#define CC 64
#define SLABS 16
#define GRID (BB * SLABS)                  // 1024 blocks -> single resident wave
#define THREADS 256
#define NTOT (NN * CC)                     // 1,048,576 floats per sample
#define F4_PER_B (NTOT / 4)                // 262,144 float4 per sample
#define F4_PER_SLAB (F4_PER_B / SLABS)     // 16,384 float4 per slab (256 KB)
#define ITERS (F4_PER_SLAB / THREADS)      // 64
#define PF_START 16                        // prefetch region k = [16, 32)
#define PF_END   32

// __device__ scratch (no allocations). Counters MONOTONIC across graph
// replays (never reset); epochs derived from tickets -> replay-safe.
__device__ float g_psum[BB][SLABS][CC];
__device__ float g_psq [BB][SLABS][CC];
__device__ unsigned long long g_done[BB];     // +SLABS per sample per launch
__device__ unsigned long long g_tick[BB];     // +SLABS per sample per launch

__global__ __launch_bounds__(THREADS, 8) void fused_kernel(const float* __restrict__ x,
                                                           const float* __restrict__ alpha_u,
                                                           const float* __restrict__ noise,
                                                           const int*   __restrict__ dom,
                                                           const int*   __restrict__ cls,
                                                           float* __restrict__ out) {
    const int tid  = threadIdx.x;
    const int b    = blockIdx.x >> 4;        // / SLABS
    const int slab = blockIdx.x & 15;        // % SLABS
    const float4* __restrict__ x4 = reinterpret_cast<const float4*>(x);
    float4* __restrict__ o4 = reinterpret_cast<float4*>(out);
    const long base = (long)b * F4_PER_B + (long)slab * F4_PER_SLAB;

    __shared__ float4 ssum[THREADS];                    // 4 KB
    __shared__ float4 ssq [THREADS];                    // 4 KB
    __shared__ float4 s_scale4[CC / 4];                 // 16B-aligned by type
    __shared__ float4 s_bias4 [CC / 4];
    __shared__ int    s_idx;
    __shared__ unsigned long long s_target;

    // ---- partner argmax (warp 0) + epoch ticket (warp 1): BEFORE streaming --
    if (tid < 32) {
        const int cb = cls[b];
        const int db = dom[b];
        float best = -INFINITY;
        int   bi   = -1;
        #pragma unroll
        for (int h = 0; h < 2; h++) {
            const int j = h * 32 + tid;
            const bool valid = (cls[j] == cb) && (dom[j] != db);
            float v = valid ? __ldg(&noise[b * BB + j]) : -INFINITY;
            float m = v; int mi = (v == -INFINITY) ? -1 : j;
            #pragma unroll
            for (int off = 16; off > 0; off >>= 1) {
                float om = __shfl_down_sync(0xffffffffu, m, off);
                int   oi = __shfl_down_sync(0xffffffffu, mi, off);
                if (om > m || (om == m && oi >= 0 && (mi < 0 || oi < mi))) { m = om; mi = oi; }
            }
            if (tid == 0) {
                if (m > best || (m == best && mi >= 0 && (bi < 0 || mi < bi))) { best = m; bi = mi; }
            }
        }
        if (tid == 0) s_idx = (bi < 0) ? b : bi;
    }
    if (tid == 32) {
        unsigned long long t = atomicAdd(&g_tick[b], 1ULL);
        s_target = (t / (unsigned long long)SLABS + 1ULL) * (unsigned long long)SLABS;
    }

    // ======= Phase 1: stats for own 256KB slab (ascending stream) ===========
    {
        float4 s = make_float4(0.f, 0.f, 0.f, 0.f);
        float4 q = make_float4(0.f, 0.f, 0.f, 0.f);
        #pragma unroll 8
        for (int k = 0; k < ITERS; k++) {
            float4 v = __ldg(&x4[base + (long)k * THREADS + tid]);
            s.x += v.x; s.y += v.y; s.z += v.z; s.w += v.w;
            q.x = fmaf(v.x, v.x, q.x);
            q.y = fmaf(v.y, v.y, q.y);
            q.z = fmaf(v.z, v.z, q.z);
            q.w = fmaf(v.w, v.w, q.w);
        }
        ssum[tid] = s;
        ssq [tid] = q;
    }
    __syncthreads();

    if (tid < 16) {   // 16 channel-quads; fold 16 partials each
        float4 S = make_float4(0.f, 0.f, 0.f, 0.f);
        float4 Q = make_float4(0.f, 0.f, 0.f, 0.f);
        #pragma unroll
        for (int m = 0; m < 16; m++) {
            float4 a = ssum[tid + 16 * m];
            float4 c = ssq [tid + 16 * m];
            S.x += a.x; S.y += a.y; S.z += a.z; S.w += a.w;
            Q.x += c.x; Q.y += c.y; Q.z += c.z; Q.w += c.w;
        }
        const int c0 = tid * 4;
        g_psum[b][slab][c0 + 0] = S.x;
        g_psum[b][slab][c0 + 1] = S.y;
        g_psum[b][slab][c0 + 2] = S.z;
        g_psum[b][slab][c0 + 3] = S.w;
        g_psq [b][slab][c0 + 0] = Q.x;
        g_psq [b][slab][c0 + 1] = Q.y;
        g_psq [b][slab][c0 + 2] = Q.z;
        g_psq [b][slab][c0 + 3] = Q.w;
        __threadfence();                     // partials visible device-wide
    }
    __syncthreads();
    if (tid == 0) atomicAdd(&g_done[b], 1ULL);

    // ---- Bubble filler: prefetch the mid region phase 2 will re-read -------
    // (k in [PF_START, PF_END): consumed right after the L2-hot tail; 64 MB
    //  chip-wide -> does not displace the tail harvest.)
    #pragma unroll
    for (int k = PF_START; k < PF_END; k++) {
        const float4* p = &x4[base + (long)k * THREADS + tid];
        asm volatile("prefetch.global.L2 [%0];" :: "l"(p));
    }

    // ---- wait for own + partner stats (single wave -> tight spread) --------
    const int idx = s_idx;
    if (tid == 0) {
        const unsigned long long target = s_target;
        for (;;) {
            unsigned long long va, vb;
            asm volatile("ld.global.acquire.gpu.u64 %0, [%1];"
                         : "=l"(va) : "l"(&g_done[b]) : "memory");
            asm volatile("ld.global.acquire.gpu.u64 %0, [%1];"
                         : "=l"(vb) : "l"(&g_done[idx]) : "memory");
            if (va >= target && vb >= target) break;
            __nanosleep(32);
        }
        __threadfence();
    }
    __syncthreads();

    // ---- scale/bias for sample b (partials are L2-hot) ----------------------
    if (tid < CC) {
        const int c = tid;
        float sum = 0.f, sq = 0.f, sum2 = 0.f, sq2 = 0.f;
        #pragma unroll
        for (int sl = 0; sl < SLABS; sl++) {
            sum  += g_psum[b][sl][c];
            sq   += g_psq [b][sl][c];
            sum2 += g_psum[idx][sl][c];
            sq2  += g_psq [idx][sl][c];
        }
        const float inv_n   = 1.0f / 16384.0f;
        const float inv_nm1 = 1.0f / 16383.0f;
        const float eps = 1e-6f;

        float mu   = sum * inv_n;
        float var  = (sq  - sum  * sum  * inv_n) * inv_nm1;
        float sig  = sqrtf(var + eps);
        float mu2  = sum2 * inv_n;
        float var2 = (sq2 - sum2 * sum2 * inv_n) * inv_nm1;
        float sig2 = sqrtf(var2 + eps);

        float a = alpha_u[b] * 0.5f;         // ALPHA_MAX
        float mu_mix  = mu  * a + mu2  * (1.0f - a);
        float sig_mix = sig * a + sig2 * (1.0f - a);

        float sc = sig_mix / sig;
        reinterpret_cast<float*>(s_scale4)[c] = sc;
        reinterpret_cast<float*>(s_bias4 )[c] = mu_mix - mu * sc;
    }
    __syncthreads();

    // ======= Phase 2: apply over the SAME region, DESCENDING ================
    // (tail of phase-1 reads is L2-freshest chip-wide -> consume it first;
    //  the prefetched mid region follows; the cold head comes last)
    const int cq = tid & 15;                 // fixed channel-quad per thread
    const float4 scl = s_scale4[cq];
    const float4 bia = s_bias4 [cq];

    #pragma unroll 4
    for (int k = ITERS - 1; k >= 0; k--) {
        const long i4 = base + (long)k * THREADS + tid;
        float4 v = __ldcs(&x4[i4]);          // dead after read -> evict-first
        float4 r;
        r.x = fmaf(v.x, scl.x, bia.x);
        r.y = fmaf(v.y, scl.y, bia.y);
        r.z = fmaf(v.z, scl.z, bia.z);
        r.w = fmaf(v.w, scl.w, bia.w);
        __stcs(&o4[i4], r);                  // never re-read -> evict-first
    }
}

extern "C" void kernel_launch(void* const* d_in, const int* in_sizes, int n_in,
                              void* d_out, int out_size) {
    const float* x       = (const float*)d_in[0];
    const float* alpha_u = (const float*)d_in[1];
    const float* noise   = (const float*)d_in[2];
    const int*   dom     = (const int*)  d_in[3];
    const int*   cls     = (const int*)  d_in[4];
    float* out = (float*)d_out;

    fused_kernel<<<GRID, THREADS>>>(x, alpha_u, noise, dom, cls, out);
}

// round 17
// speedup vs baseline: 1.0325x; 1.0312x over previous
#include <cuda_runtime.h>
#include <math.h>

#define BB 64
#define NN 16384
#define CC 64
#define SLABS 16
#define GRID (BB * SLABS)                  // 1024 blocks -> single resident wave
#define THREADS 256
#define NTOT (NN * CC)                     // 1,048,576 floats per sample
#define F4_PER_B (NTOT / 4)                // 262,144 float4 per sample
#define F4_PER_SLAB (F4_PER_B / SLABS)     // 16,384 float4 per slab (256 KB)
#define ITERS (F4_PER_SLAB / THREADS)      // 64

// __device__ scratch (no allocations). Counters MONOTONIC across graph
// replays (never reset); epochs derived from tickets -> replay-safe.
__device__ float g_psum[BB][SLABS][CC];
__device__ float g_psq [BB][SLABS][CC];
__device__ unsigned long long g_done[BB];     // +SLABS per sample per launch
__device__ unsigned long long g_tick[BB];     // +SLABS per sample per launch

__global__ __launch_bounds__(THREADS, 8) void fused_kernel(const float* __restrict__ x,
                                                           const float* __restrict__ alpha_u,
                                                           const float* __restrict__ noise,
                                                           const int*   __restrict__ dom,
                                                           const int*   __restrict__ cls,
                                                           float* __restrict__ out) {
    const int tid  = threadIdx.x;
    const int b    = blockIdx.x >> 4;        // / SLABS
    const int slab = blockIdx.x & 15;        // % SLABS
    const float4* __restrict__ x4 = reinterpret_cast<const float4*>(x);
    float4* __restrict__ o4 = reinterpret_cast<float4*>(out);
    const long base = (long)b * F4_PER_B + (long)slab * F4_PER_SLAB;

    __shared__ float4 ssum[THREADS];                    // 4 KB
    __shared__ float4 ssq [THREADS];                    // 4 KB
    __shared__ float4 s_scale4[CC / 4];                 // 16B-aligned by type
    __shared__ float4 s_bias4 [CC / 4];
    __shared__ int    s_idx;
    __shared__ unsigned long long s_target;

    // ---- partner argmax (warp 0) + epoch ticket (warp 1): BEFORE streaming,
    //      so their latency hides at kernel start instead of in the bubble ----
    if (tid < 32) {
        const int cb = cls[b];
        const int db = dom[b];
        float best = -INFINITY;
        int   bi   = -1;
        #pragma unroll
        for (int h = 0; h < 2; h++) {
            const int j = h * 32 + tid;
            const bool valid = (cls[j] == cb) && (dom[j] != db);
            float v = valid ? __ldg(&noise[b * BB + j]) : -INFINITY;
            float m = v; int mi = (v == -INFINITY) ? -1 : j;
            #pragma unroll
            for (int off = 16; off > 0; off >>= 1) {
                float om = __shfl_down_sync(0xffffffffu, m, off);
                int   oi = __shfl_down_sync(0xffffffffu, mi, off);
                if (om > m || (om == m && oi >= 0 && (mi < 0 || oi < mi))) { m = om; mi = oi; }
            }
            if (tid == 0) {
                if (m > best || (m == best && mi >= 0 && (bi < 0 || mi < bi))) { best = m; bi = mi; }
            }
        }
        if (tid == 0) s_idx = (bi < 0) ? b : bi;
    }
    if (tid == 32) {
        unsigned long long t = atomicAdd(&g_tick[b], 1ULL);
        s_target = (t / (unsigned long long)SLABS + 1ULL) * (unsigned long long)SLABS;
    }

    // ======= Phase 1: stats for own 256KB slab (ascending stream) ===========
    {
        float4 s = make_float4(0.f, 0.f, 0.f, 0.f);
        float4 q = make_float4(0.f, 0.f, 0.f, 0.f);
        #pragma unroll 8
        for (int k = 0; k < ITERS; k++) {
            float4 v = __ldg(&x4[base + (long)k * THREADS + tid]);
            s.x += v.x; s.y += v.y; s.z += v.z; s.w += v.w;
            q.x = fmaf(v.x, v.x, q.x);
            q.y = fmaf(v.y, v.y, q.y);
            q.z = fmaf(v.z, v.z, q.z);
            q.w = fmaf(v.w, v.w, q.w);
        }
        ssum[tid] = s;
        ssq [tid] = q;
    }
    __syncthreads();

    if (tid < 16) {   // 16 channel-quads; fold 16 partials each
        float4 S = make_float4(0.f, 0.f, 0.f, 0.f);
        float4 Q = make_float4(0.f, 0.f, 0.f, 0.f);
        #pragma unroll
        for (int m = 0; m < 16; m++) {
            float4 a = ssum[tid + 16 * m];
            float4 c = ssq [tid + 16 * m];
            S.x += a.x; S.y += a.y; S.z += a.z; S.w += a.w;
            Q.x += c.x; Q.y += c.y; Q.z += c.z; Q.w += c.w;
        }
        const int c0 = tid * 4;
        g_psum[b][slab][c0 + 0] = S.x;
        g_psum[b][slab][c0 + 1] = S.y;
        g_psum[b][slab][c0 + 2] = S.z;
        g_psum[b][slab][c0 + 3] = S.w;
        g_psq [b][slab][c0 + 0] = Q.x;
        g_psq [b][slab][c0 + 1] = Q.y;
        g_psq [b][slab][c0 + 2] = Q.z;
        g_psq [b][slab][c0 + 3] = Q.w;
        __threadfence();                     // partials visible device-wide
    }
    __syncthreads();
    if (tid == 0) atomicAdd(&g_done[b], 1ULL);

    // ---- wait for own + partner stats (single wave -> tight spread) --------
    const int idx = s_idx;
    if (tid == 0) {
        const unsigned long long target = s_target;
        for (;;) {
            unsigned long long va, vb;
            asm volatile("ld.global.acquire.gpu.u64 %0, [%1];"
                         : "=l"(va) : "l"(&g_done[b]) : "memory");
            asm volatile("ld.global.acquire.gpu.u64 %0, [%1];"
                         : "=l"(vb) : "l"(&g_done[idx]) : "memory");
            if (va >= target && vb >= target) break;
            __nanosleep(32);
        }
        __threadfence();
    }
    __syncthreads();

    // ---- scale/bias for sample b (partials are L2-hot) ----------------------
    if (tid < CC) {
        const int c = tid;
        float sum = 0.f, sq = 0.f, sum2 = 0.f, sq2 = 0.f;
        #pragma unroll
        for (int sl = 0; sl < SLABS; sl++) {
            sum  += g_psum[b][sl][c];
            sq   += g_psq [b][sl][c];
            sum2 += g_psum[idx][sl][c];
            sq2  += g_psq [idx][sl][c];
        }
        const float inv_n   = 1.0f / 16384.0f;
        const float inv_nm1 = 1.0f / 16383.0f;
        const float eps = 1e-6f;

        float mu   = sum * inv_n;
        float var  = (sq  - sum  * sum  * inv_n) * inv_nm1;
        float sig  = sqrtf(var + eps);
        float mu2  = sum2 * inv_n;
        float var2 = (sq2 - sum2 * sum2 * inv_n) * inv_nm1;
        float sig2 = sqrtf(var2 + eps);

        float a = alpha_u[b] * 0.5f;         // ALPHA_MAX
        float mu_mix  = mu  * a + mu2  * (1.0f - a);
        float sig_mix = sig * a + sig2 * (1.0f - a);

        float sc = sig_mix / sig;
        reinterpret_cast<float*>(s_scale4)[c] = sc;
        reinterpret_cast<float*>(s_bias4 )[c] = mu_mix - mu * sc;
    }
    __syncthreads();

    // ======= Phase 2: apply over the SAME region, DESCENDING ================
    // (tail of phase-1 reads is L2-freshest chip-wide -> consume it first)
    const int cq = tid & 15;                 // fixed channel-quad per thread
    const float4 scl = s_scale4[cq];
    const float4 bia = s_bias4 [cq];

    #pragma unroll 4
    for (int k = ITERS - 1; k >= 0; k--) {
        const long i4 = base + (long)k * THREADS + tid;
        float4 v = __ldcs(&x4[i4]);          // dead after read -> evict-first
        float4 r;
        r.x = fmaf(v.x, scl.x, bia.x);
        r.y = fmaf(v.y, scl.y, bia.y);
        r.z = fmaf(v.z, scl.z, bia.z);
        r.w = fmaf(v.w, scl.w, bia.w);
        __stcs(&o4[i4], r);                  // never re-read -> evict-first
    }
}

extern "C" void kernel_launch(void* const* d_in, const int* in_sizes, int n_in,
                              void* d_out, int out_size) {
    const float* x       = (const float*)d_in[0];
    const float* alpha_u = (const float*)d_in[1];
    const float* noise   = (const float*)d_in[2];
    const int*   dom     = (const int*)  d_in[3];
    const int*   cls     = (const int*)  d_in[4];
    float* out = (float*)d_out;

    fused_kernel<<<GRID, THREADS>>>(x, alpha_u, noise, dom, cls, out);
}